// round 2
// baseline (speedup 1.0000x reference)
#include <cuda_runtime.h>
#include <math.h>

#define NTOT   8192
#define BHALF  4096
#define DDIM   256
#define NQ     64          // float4 quads per row (256/4)
#define TILE   64
#define KSTR   68          // padded floats per k-slice (64 + 4), keeps 16B alignment
#define SMEM_FLOATS (2 * DDIM * KSTR)
#define SMEM_BYTES  (SMEM_FLOATS * 4)

// Scratch (allocation-free: device globals)
__device__ float g_zn[NTOT * DDIM];   // normalized, pre-scaled by 1/sqrt(T)
__device__ float g_lse[NTOT];
__device__ float g_loss[NTOT];

// ---------------------------------------------------------------------------
// Kernel 1: row-normalize z = [z_i; z_j], scale by 1/sqrt(0.1) so that
// dot(zn_a, zn_b) = cos(a,b)/T directly.
// One warp per row; lane holds 2 float4 (8 floats).
// ---------------------------------------------------------------------------
__global__ void normalize_kernel(const float* __restrict__ z_i,
                                 const float* __restrict__ z_j) {
    int row  = blockIdx.x * blockDim.y + threadIdx.y;
    int lane = threadIdx.x;
    const float* src = (row < BHALF) ? (z_i + (size_t)row * DDIM)
                                     : (z_j + (size_t)(row - BHALF) * DDIM);
    const float4* s4 = (const float4*)src;
    float4 v0 = s4[lane];
    float4 v1 = s4[lane + 32];
    float ss = v0.x*v0.x + v0.y*v0.y + v0.z*v0.z + v0.w*v0.w
             + v1.x*v1.x + v1.y*v1.y + v1.z*v1.z + v1.w*v1.w;
    #pragma unroll
    for (int o = 16; o > 0; o >>= 1) ss += __shfl_xor_sync(0xffffffffu, ss, o);
    // 1/max(||z||, eps) * 1/sqrt(TEMPERATURE)
    float sc = 3.1622776601683795f / fmaxf(sqrtf(ss), 1e-8f);
    v0.x *= sc; v0.y *= sc; v0.z *= sc; v0.w *= sc;
    v1.x *= sc; v1.y *= sc; v1.z *= sc; v1.w *= sc;
    float4* d4 = (float4*)(g_zn + (size_t)row * DDIM);
    d4[lane]      = v0;
    d4[lane + 32] = v1;
}

// ---------------------------------------------------------------------------
// Shared-memory tile loader: 64 rows x 256 k, stored k-major with stride KSTR.
// Warp covers 8 rows x 4 quads per iteration:
//   - global: 4 consecutive quads (64B) per row segment -> coalesced enough
//   - STS banks: (16*kq + 4i + row) mod 32 spans 16 banks -> 2-way conflict
// ---------------------------------------------------------------------------
__device__ __forceinline__ void load_tile(float* __restrict__ dst,
                                          const float* __restrict__ src,
                                          int lane, int warp) {
    const float4* src4 = (const float4*)src;
    #pragma unroll
    for (int it = 0; it < 16; ++it) {
        int wt   = it * 8 + warp;        // 0..127 warp-tiles
        int rowT = wt & 7;               // 8 row-tiles of 8 rows
        int kqT  = wt >> 3;              // 16 kq-tiles of 4 quads
        int row  = rowT * 8 + (lane >> 2);
        int kq   = kqT * 4 + (lane & 3);
        float4 v = src4[row * NQ + kq];
        int k0 = kq * 4;
        dst[(k0 + 0) * KSTR + row] = v.x;
        dst[(k0 + 1) * KSTR + row] = v.y;
        dst[(k0 + 2) * KSTR + row] = v.z;
        dst[(k0 + 3) * KSTR + row] = v.w;
    }
}

// ---------------------------------------------------------------------------
// Kernel 2: fused sim-GEMM + online row-wise logsumexp (diag excluded).
// Block = 64 rows; loops over 128 column chunks of 64. 256 threads,
// 16x16 thread grid, each thread owns a 4x4 micro-tile.
// ---------------------------------------------------------------------------
__global__ __launch_bounds__(256, 1)
void gemm_lse_kernel() {
    extern __shared__ float smem[];
    float* As = smem;
    float* Bs = smem + DDIM * KSTR;

    int tid  = threadIdx.x;
    int lane = tid & 31;
    int warp = tid >> 5;
    int r    = tid >> 4;    // 0..15: rows 4r..4r+3
    int c    = tid & 15;    // 0..15: cols 4c..4c+3
    int row0 = blockIdx.x * TILE;

    load_tile(As, g_zn + (size_t)row0 * DDIM, lane, warp);

    const float NEGINF = __int_as_float(0xff800000);
    float m_run[4], s_run[4];
    #pragma unroll
    for (int i = 0; i < 4; ++i) { m_run[i] = NEGINF; s_run[i] = 0.0f; }

    const float4* As4 = (const float4*)As;   // quad stride per k = KSTR/4 = 17
    const float4* Bs4 = (const float4*)Bs;

    for (int cb = 0; cb < NTOT / TILE; ++cb) {
        __syncthreads();   // previous compute done (and A tile visible on cb==0)
        load_tile(Bs, g_zn + (size_t)cb * TILE * DDIM, lane, warp);
        __syncthreads();

        float acc[4][4];
        #pragma unroll
        for (int i = 0; i < 4; ++i)
            #pragma unroll
            for (int j = 0; j < 4; ++j) acc[i][j] = 0.0f;

        #pragma unroll 4
        for (int k = 0; k < DDIM; ++k) {
            float4 a = As4[k * 17 + r];
            float4 b = Bs4[k * 17 + c];
            float av[4] = {a.x, a.y, a.z, a.w};
            float bv[4] = {b.x, b.y, b.z, b.w};
            #pragma unroll
            for (int i = 0; i < 4; ++i)
                #pragma unroll
                for (int j = 0; j < 4; ++j)
                    acc[i][j] = fmaf(av[i], bv[j], acc[i][j]);
        }

        // Diagonal mask: tiles are 64-aligned on both axes, so the diagonal
        // only appears when cb == blockIdx.x, at local (4r+i == 4c+j).
        if (cb == (int)blockIdx.x && r == c) {
            acc[0][0] = -1e30f; acc[1][1] = -1e30f;
            acc[2][2] = -1e30f; acc[3][3] = -1e30f;
        }

        // Online LSE update; row is spread over the 16 lanes sharing r
        // (xor offsets 1,2,4,8 stay inside the 16-lane group).
        #pragma unroll
        for (int i = 0; i < 4; ++i) {
            float mc = fmaxf(fmaxf(acc[i][0], acc[i][1]),
                             fmaxf(acc[i][2], acc[i][3]));
            #pragma unroll
            for (int o = 8; o > 0; o >>= 1)
                mc = fmaxf(mc, __shfl_xor_sync(0xffffffffu, mc, o));
            float newm = fmaxf(m_run[i], mc);
            float sum = __expf(acc[i][0] - newm) + __expf(acc[i][1] - newm)
                      + __expf(acc[i][2] - newm) + __expf(acc[i][3] - newm);
            #pragma unroll
            for (int o = 8; o > 0; o >>= 1)
                sum += __shfl_xor_sync(0xffffffffu, sum, o);
            s_run[i] = s_run[i] * __expf(m_run[i] - newm) + sum;
            m_run[i] = newm;
        }
    }

    if (c == 0) {
        #pragma unroll
        for (int i = 0; i < 4; ++i)
            g_lse[row0 + 4 * r + i] = m_run[i] + logf(s_run[i]);
    }
}

// ---------------------------------------------------------------------------
// Kernel 3: per-row loss = lse_k - dot(zn_k, zn_pos(k))   (one warp per row)
// ---------------------------------------------------------------------------
__global__ void finalize_kernel() {
    int row  = blockIdx.x * blockDim.y + threadIdx.y;
    int lane = threadIdx.x;
    int pos  = (row < BHALF) ? row + BHALF : row - BHALF;
    const float4* a4 = (const float4*)(g_zn + (size_t)row * DDIM);
    const float4* b4 = (const float4*)(g_zn + (size_t)pos * DDIM);
    float dot = 0.0f;
    #pragma unroll
    for (int t = 0; t < 2; ++t) {
        float4 a = a4[lane + 32 * t];
        float4 b = b4[lane + 32 * t];
        dot += a.x*b.x + a.y*b.y + a.z*b.z + a.w*b.w;
    }
    #pragma unroll
    for (int o = 16; o > 0; o >>= 1) dot += __shfl_xor_sync(0xffffffffu, dot, o);
    if (lane == 0) g_loss[row] = g_lse[row] - dot;
}

// ---------------------------------------------------------------------------
// Kernel 4: deterministic masked mean (single block, fixed reduction order).
// mask_positive is a bool input -> delivered as int32 by the harness.
// ---------------------------------------------------------------------------
__global__ void reduce_kernel(const int* __restrict__ mask,
                              float* __restrict__ out) {
    __shared__ float ssum[256];
    __shared__ float scnt[256];
    int tid = threadIdx.x;
    float sum = 0.0f, cnt = 0.0f;
    for (int k = tid; k < NTOT; k += 256) {
        if (mask[k & (BHALF - 1)] != 0) { sum += g_loss[k]; cnt += 1.0f; }
    }
    ssum[tid] = sum; scnt[tid] = cnt;
    __syncthreads();
    for (int s = 128; s > 0; s >>= 1) {
        if (tid < s) { ssum[tid] += ssum[tid + s]; scnt[tid] += scnt[tid + s]; }
        __syncthreads();
    }
    if (tid == 0)
        out[0] = (scnt[0] > 0.0f) ? ssum[0] / fmaxf(scnt[0], 1.0f) : 0.0f;
}

// ---------------------------------------------------------------------------
extern "C" void kernel_launch(void* const* d_in, const int* in_sizes, int n_in,
                              void* d_out, int out_size) {
    const float* z_i  = (const float*)d_in[0];
    const float* z_j  = (const float*)d_in[1];
    const int*   mask = (const int*)d_in[2];
    float* out = (float*)d_out;

    (void)in_sizes; (void)n_in; (void)out_size;

    // Host-side attribute set (executes immediately; not a stream op — safe
    // under graph capture, idempotent across calls).
    cudaFuncSetAttribute(gemm_lse_kernel,
                         cudaFuncAttributeMaxDynamicSharedMemorySize,
                         SMEM_BYTES);

    dim3 warpBlock(32, 8);
    normalize_kernel<<<NTOT / 8, warpBlock>>>(z_i, z_j);
    gemm_lse_kernel<<<NTOT / TILE, 256, SMEM_BYTES>>>();
    finalize_kernel<<<NTOT / 8, warpBlock>>>();
    reduce_kernel<<<1, 256>>>(mask, out);
}

// round 4
// speedup vs baseline: 11.4089x; 11.4089x over previous
#include <cuda_runtime.h>
#include <cuda_bf16.h>
#include <cstdint>
#include <math.h>

#define NTOT   8192
#define BHALF  4096
#define DDIM   256
#define MT     128
#define NC     128
#define NCHUNKS 32
#define TILEB  65536              // 128 rows * 512 B
#define SMEM_TOTAL (3 * TILEB)    // A + B0 + B1 = 192 KB

// ---------------- scratch (device globals; allocation-free) ----------------
__device__ __align__(16) float          g_zn [NTOT * DDIM];  // fp32 * 1/sqrt(T)
__device__ __align__(16) __nv_bfloat16  g_znb[NTOT * DDIM];  // bf16 * sqrt(10*log2 e)
__device__ float g_s[2][NTOT];
__device__ float g_loss[NTOT];

// ---------------- helpers (baseline PTX only: sm_80-class) ----------------
__device__ __forceinline__ uint32_t s2u(const void* p) {
    return (uint32_t)__cvta_generic_to_shared(p);
}
__device__ __forceinline__ void cp16(uint32_t dst, const void* src) {
    asm volatile("cp.async.cg.shared.global [%0], [%1], 16;"
                 :: "r"(dst), "l"(src) : "memory");
}
__device__ __forceinline__ void cp_commit() {
    asm volatile("cp.async.commit_group;" ::: "memory");
}
template <int N> __device__ __forceinline__ void cp_wait() {
    asm volatile("cp.async.wait_group %0;" :: "n"(N) : "memory");
}
__device__ __forceinline__ float ex2(float x) {
    float r;
    asm("ex2.approx.ftz.f32 %0, %1;" : "=f"(r) : "f"(x));
    return r;
}
#define LDSM4(r0, r1, r2, r3, addr)                                           \
    asm volatile("ldmatrix.sync.aligned.m8n8.x4.shared.b16 {%0,%1,%2,%3}, [%4];" \
                 : "=r"(r0), "=r"(r1), "=r"(r2), "=r"(r3) : "r"(addr))
#define MMA16816(d, a, b)                                                     \
    asm volatile("mma.sync.aligned.m16n8k16.row.col.f32.bf16.bf16.f32 "       \
                 "{%0,%1,%2,%3},{%4,%5,%6,%7},{%8,%9},{%0,%1,%2,%3};"         \
                 : "+f"((d)[0]), "+f"((d)[1]), "+f"((d)[2]), "+f"((d)[3])     \
                 : "r"((a)[0]), "r"((a)[1]), "r"((a)[2]), "r"((a)[3]),        \
                   "r"((b)[0]), "r"((b)[1]))

// 16B-unit XOR swizzle: unit index within row = u ^ (row & 7)
__device__ __forceinline__ uint32_t sw_off(int row, int u) {
    return (uint32_t)((row * 32 + (u ^ (row & 7))) << 4);
}

// Load a 128-row x 512-byte tile via cp.async (64 KB), 256 threads.
__device__ __forceinline__ void load_tile_async(uint32_t smem_base,
                                                const __nv_bfloat16* src,
                                                int tid) {
    const char* s = (const char*)src;
    #pragma unroll
    for (int i = 0; i < 16; ++i) {
        int g   = i * 256 + tid;
        int row = g >> 5;
        int u   = g & 31;
        cp16(smem_base + sw_off(row, u), s + row * 512 + u * 16);
    }
}

// ---------------------------------------------------------------------------
// Kernel 1: normalize. fp32 copy * 1/sqrt(T); bf16 copy * sqrt(10*log2 e)
// so bf16 dot = cos * 10 * log2(e) = exp2 argument directly.
// ---------------------------------------------------------------------------
__global__ void normalize_kernel(const float* __restrict__ z_i,
                                 const float* __restrict__ z_j) {
    int row  = blockIdx.x * blockDim.y + threadIdx.y;
    int lane = threadIdx.x;
    const float* src = (row < BHALF) ? (z_i + (size_t)row * DDIM)
                                     : (z_j + (size_t)(row - BHALF) * DDIM);
    const float4* s4 = (const float4*)src;
    float4 v0 = s4[lane];
    float4 v1 = s4[lane + 32];
    float ss = v0.x*v0.x + v0.y*v0.y + v0.z*v0.z + v0.w*v0.w
             + v1.x*v1.x + v1.y*v1.y + v1.z*v1.z + v1.w*v1.w;
    #pragma unroll
    for (int o = 16; o > 0; o >>= 1) ss += __shfl_xor_sync(0xffffffffu, ss, o);
    float inv = 1.0f / fmaxf(sqrtf(ss), 1e-8f);
    float scf = 3.1622776601683795f * inv;   // 1/sqrt(0.1)
    float scb = 3.7982829f * inv;            // sqrt(10*log2(e))

    float4* d4 = (float4*)(g_zn + (size_t)row * DDIM);
    float4 w0 = { v0.x*scf, v0.y*scf, v0.z*scf, v0.w*scf };
    float4 w1 = { v1.x*scf, v1.y*scf, v1.z*scf, v1.w*scf };
    d4[lane]      = w0;
    d4[lane + 32] = w1;

    uint2 b0, b1;
    *(__nv_bfloat162*)&b0.x = __floats2bfloat162_rn(v0.x*scb, v0.y*scb);
    *(__nv_bfloat162*)&b0.y = __floats2bfloat162_rn(v0.z*scb, v0.w*scb);
    *(__nv_bfloat162*)&b1.x = __floats2bfloat162_rn(v1.x*scb, v1.y*scb);
    *(__nv_bfloat162*)&b1.y = __floats2bfloat162_rn(v1.z*scb, v1.w*scb);
    uint2* db = (uint2*)(g_znb + (size_t)row * DDIM);
    db[lane]      = b0;
    db[lane + 32] = b1;
}

// ---------------------------------------------------------------------------
// Kernel 2: bf16 mma.sync GEMM + fused sum-of-exp2 epilogue.
// Grid: 128 CTAs = 64 row-tiles x 2 column-halves. 256 threads = 8 warps
// in a 4x2 (M x N) grid; each warp computes 32x64 per 128-col chunk.
// ---------------------------------------------------------------------------
__global__ __launch_bounds__(256, 1) void gemm_lse_hmma() {
    extern __shared__ __align__(1024) char smem[];
    char* Asm = smem;
    char* Bsm[2] = { smem + TILEB, smem + 2 * TILEB };

    const int tid  = threadIdx.x;
    const int w    = tid >> 5;
    const int lane = tid & 31;
    const int wx   = w & 3;           // M position (32-row band)
    const int wy   = w >> 2;          // N position (64-col band)

    const int mtile  = blockIdx.x >> 1;
    const int h      = blockIdx.x & 1;
    const int m0     = mtile * MT;
    const int n_base = h * (NTOT / 2);
    const int cdiag  = ((m0 >> 12) == h) ? ((m0 & 4095) >> 7) : -1;

    // --- prologue: A tile + B chunk 0 ---
    const uint32_t Abase = s2u(Asm);
    const uint32_t Bbase0 = s2u(Bsm[0]);
    const uint32_t Bbase1 = s2u(Bsm[1]);
    load_tile_async(Abase, g_znb + (size_t)m0 * DDIM, tid);
    load_tile_async(Bbase0, g_znb + (size_t)n_base * DDIM, tid);
    cp_commit();

    // precomputed ldmatrix lane geometry
    const int tile  = lane >> 3;
    const int l7    = lane & 7;
    // A: tile0=(m-lo,k-lo) tile1=(m-hi,k-lo) tile2=(m-lo,k-hi) tile3=(m-hi,k-hi)
    const int a_row = wx * 32 + (tile & 1) * 8 + l7;        // + mt*16
    const int a_kh  = tile >> 1;                            // k half (unit)
    // B: tile0=(n-lo,k-lo) tile1=(n-lo,k-hi) tile2=(n-hi,k-lo) tile3=(n-hi,k-hi)
    const int b_row = wy * 64 + (tile >> 1) * 8 + l7;       // + np*16
    const int b_kh  = tile & 1;

    float rsum[2][2] = {{0.f, 0.f}, {0.f, 0.f}};   // [mt][row-half]

    for (int c = 0; c < NCHUNKS; ++c) {
        if (c + 1 < NCHUNKS) {
            load_tile_async((c & 1) ? Bbase0 : Bbase1,
                            g_znb + (size_t)(n_base + (c + 1) * NC) * DDIM, tid);
            cp_commit();
            cp_wait<1>();
        } else {
            cp_wait<0>();
        }
        __syncthreads();

        const uint32_t Bb = (c & 1) ? Bbase1 : Bbase0;

        float acc[2][8][4];
        #pragma unroll
        for (int mt = 0; mt < 2; ++mt)
            #pragma unroll
            for (int nt = 0; nt < 8; ++nt)
                #pragma unroll
                for (int j = 0; j < 4; ++j) acc[mt][nt][j] = 0.f;

        #pragma unroll
        for (int ks = 0; ks < 16; ++ks) {
            uint32_t a[2][4];
            #pragma unroll
            for (int mt = 0; mt < 2; ++mt) {
                int row = a_row + mt * 16;
                int ku  = ks * 2 + a_kh;
                LDSM4(a[mt][0], a[mt][1], a[mt][2], a[mt][3],
                      Abase + sw_off(row, ku));
            }
            uint32_t b[8][2];
            #pragma unroll
            for (int np = 0; np < 4; ++np) {
                int row = b_row + np * 16;
                int ku  = ks * 2 + b_kh;
                uint32_t r0, r1, r2, r3;
                LDSM4(r0, r1, r2, r3, Bb + sw_off(row, ku));
                b[2*np][0] = r0;  b[2*np][1] = r1;
                b[2*np+1][0] = r2; b[2*np+1][1] = r3;
            }
            #pragma unroll
            for (int mt = 0; mt < 2; ++mt)
                #pragma unroll
                for (int nt = 0; nt < 8; ++nt)
                    MMA16816(acc[mt][nt], a[mt], b[nt]);
        }

        // --- fused epilogue: sum of 2^acc (skip diagonal element) ---
        if (c != cdiag) {
            #pragma unroll
            for (int mt = 0; mt < 2; ++mt)
                #pragma unroll
                for (int nt = 0; nt < 8; ++nt) {
                    rsum[mt][0] += ex2(acc[mt][nt][0]) + ex2(acc[mt][nt][1]);
                    rsum[mt][1] += ex2(acc[mt][nt][2]) + ex2(acc[mt][nt][3]);
                }
        } else {
            int colb = n_base + c * NC + wy * 64 + (lane & 3) * 2;
            int rowb = m0 + wx * 32 + (lane >> 2);
            #pragma unroll
            for (int mt = 0; mt < 2; ++mt)
                #pragma unroll
                for (int nt = 0; nt < 8; ++nt)
                    #pragma unroll
                    for (int j = 0; j < 4; ++j) {
                        int col = colb + nt * 8 + (j & 1);
                        int row = rowb + mt * 16 + (j >> 1) * 8;
                        float e = ex2(acc[mt][nt][j]);
                        if (row == col) e = 0.f;
                        rsum[mt][j >> 1] += e;
                    }
        }
        __syncthreads();   // all warps done reading this B buffer
    }

    // --- reduce row sums: quad lanes share a row ---
    #pragma unroll
    for (int mt = 0; mt < 2; ++mt)
        #pragma unroll
        for (int rh = 0; rh < 2; ++rh) {
            float v = rsum[mt][rh];
            v += __shfl_xor_sync(0xffffffffu, v, 1);
            v += __shfl_xor_sync(0xffffffffu, v, 2);
            rsum[mt][rh] = v;
        }

    float* rs = (float*)Bsm[0];   // 2 x 128 floats, reuse B smem
    if ((lane & 3) == 0) {
        #pragma unroll
        for (int mt = 0; mt < 2; ++mt)
            #pragma unroll
            for (int rh = 0; rh < 2; ++rh)
                rs[wy * 128 + wx * 32 + mt * 16 + rh * 8 + (lane >> 2)]
                    = rsum[mt][rh];
    }
    __syncthreads();
    if (tid < 128)
        g_s[h][m0 + tid] = rs[tid] + rs[128 + tid];
}

// ---------------------------------------------------------------------------
// Kernel 3: loss_k = ln2 * log2(sum of 2^sim) - dot_fp32(zn_k, zn_pos)
// ---------------------------------------------------------------------------
__global__ void finalize_kernel() {
    int row  = blockIdx.x * blockDim.y + threadIdx.y;
    int lane = threadIdx.x;
    int pos  = (row < BHALF) ? row + BHALF : row - BHALF;
    const float4* a4 = (const float4*)(g_zn + (size_t)row * DDIM);
    const float4* b4 = (const float4*)(g_zn + (size_t)pos * DDIM);
    float dot = 0.0f;
    #pragma unroll
    for (int t = 0; t < 2; ++t) {
        float4 a = a4[lane + 32 * t];
        float4 b = b4[lane + 32 * t];
        dot += a.x*b.x + a.y*b.y + a.z*b.z + a.w*b.w;
    }
    #pragma unroll
    for (int o = 16; o > 0; o >>= 1) dot += __shfl_xor_sync(0xffffffffu, dot, o);
    if (lane == 0) {
        float s = g_s[0][row] + g_s[1][row];
        g_loss[row] = 0.6931471805599453f * log2f(s) - dot;
    }
}

// ---------------------------------------------------------------------------
// Kernel 4: deterministic masked mean (single block).
// ---------------------------------------------------------------------------
__global__ void reduce_kernel(const int* __restrict__ mask,
                              float* __restrict__ out) {
    __shared__ float ssum[1024];
    __shared__ float scnt[1024];
    int tid = threadIdx.x;
    float sum = 0.0f, cnt = 0.0f;
    for (int k = tid; k < NTOT; k += 1024) {
        if (mask[k & (BHALF - 1)] != 0) { sum += g_loss[k]; cnt += 1.0f; }
    }
    ssum[tid] = sum; scnt[tid] = cnt;
    __syncthreads();
    for (int s = 512; s > 0; s >>= 1) {
        if (tid < s) { ssum[tid] += ssum[tid + s]; scnt[tid] += scnt[tid + s]; }
        __syncthreads();
    }
    if (tid == 0)
        out[0] = (scnt[0] > 0.0f) ? ssum[0] / fmaxf(scnt[0], 1.0f) : 0.0f;
}

// ---------------------------------------------------------------------------
extern "C" void kernel_launch(void* const* d_in, const int* in_sizes, int n_in,
                              void* d_out, int out_size) {
    const float* z_i  = (const float*)d_in[0];
    const float* z_j  = (const float*)d_in[1];
    const int*   mask = (const int*)d_in[2];
    float* out = (float*)d_out;
    (void)in_sizes; (void)n_in; (void)out_size;

    cudaFuncSetAttribute(gemm_lse_hmma,
                         cudaFuncAttributeMaxDynamicSharedMemorySize,
                         SMEM_TOTAL);

    dim3 warpBlock(32, 8);
    normalize_kernel<<<NTOT / 8, warpBlock>>>(z_i, z_j);
    gemm_lse_hmma<<<128, 256, SMEM_TOTAL>>>();
    finalize_kernel<<<NTOT / 8, warpBlock>>>();
    reduce_kernel<<<1, 1024>>>(mask, out);
}

// round 5
// speedup vs baseline: 19.6182x; 1.7195x over previous
#include <cuda_runtime.h>
#include <cuda_bf16.h>
#include <cstdint>
#include <math.h>

#define NTOT   8192
#define BHALF  4096
#define DDIM   256
#define NBLK   64                 // 128-row blocks
#define NTILES 2080               // 64*65/2 triangle tiles
#define TILEB  65536              // 128 rows * 512 B
#define SMEM_TOTAL (3 * TILEB)    // A + B0 + B1 = 192 KB

// ---------------- scratch (device globals; allocation-free) ----------------
__device__ __align__(16) float          g_zn [NTOT * DDIM];  // fp32 * 1/sqrt(T)
__device__ __align__(16) __nv_bfloat16  g_znb[NTOT * DDIM];  // bf16 * sqrt(10*log2 e)
__device__ float  g_part[NBLK * NTOT];   // [slot][row] exp2 partial sums (2 MB)
__device__ float2 g_red[1024];           // per-finalize-block (sum, cnt)

// ---------------- helpers (baseline PTX only) ----------------
__device__ __forceinline__ uint32_t s2u(const void* p) {
    return (uint32_t)__cvta_generic_to_shared(p);
}
__device__ __forceinline__ void cp16(uint32_t dst, const void* src) {
    asm volatile("cp.async.cg.shared.global [%0], [%1], 16;"
                 :: "r"(dst), "l"(src) : "memory");
}
__device__ __forceinline__ void cp_commit() {
    asm volatile("cp.async.commit_group;" ::: "memory");
}
template <int N> __device__ __forceinline__ void cp_wait() {
    asm volatile("cp.async.wait_group %0;" :: "n"(N) : "memory");
}
__device__ __forceinline__ float ex2(float x) {
    float r;
    asm("ex2.approx.ftz.f32 %0, %1;" : "=f"(r) : "f"(x));
    return r;
}
#define LDSM4(r0, r1, r2, r3, addr)                                           \
    asm volatile("ldmatrix.sync.aligned.m8n8.x4.shared.b16 {%0,%1,%2,%3}, [%4];" \
                 : "=r"(r0), "=r"(r1), "=r"(r2), "=r"(r3) : "r"(addr))
#define MMA16816(d, a, b)                                                     \
    asm volatile("mma.sync.aligned.m16n8k16.row.col.f32.bf16.bf16.f32 "       \
                 "{%0,%1,%2,%3},{%4,%5,%6,%7},{%8,%9},{%0,%1,%2,%3};"         \
                 : "+f"((d)[0]), "+f"((d)[1]), "+f"((d)[2]), "+f"((d)[3])     \
                 : "r"((a)[0]), "r"((a)[1]), "r"((a)[2]), "r"((a)[3]),        \
                   "r"((b)[0]), "r"((b)[1]))

// 16B-unit XOR swizzle: unit index within 512B row = u ^ (row & 7)
__device__ __forceinline__ uint32_t sw_off(int row, int u) {
    return (uint32_t)((row * 32 + (u ^ (row & 7))) << 4);
}

// Load a 128-row x 512-byte block (64 KB) via cp.async, 256 threads.
__device__ __forceinline__ void load_blk(uint32_t smem_base, int blk, int tid) {
    const char* s = (const char*)(g_znb + (size_t)blk * 128 * DDIM);
    #pragma unroll
    for (int i = 0; i < 16; ++i) {
        int g   = i * 256 + tid;
        int row = g >> 5;
        int u   = g & 31;
        cp16(smem_base + sw_off(row, u), s + row * 512 + u * 16);
    }
}

// ---------------------------------------------------------------------------
// Kernel 1: normalize. fp32 copy * 1/sqrt(T); bf16 copy * sqrt(10*log2 e)
// so bf16 dot = cos * 10 * log2(e) = exp2 argument directly.
// ---------------------------------------------------------------------------
__global__ void normalize_kernel(const float* __restrict__ z_i,
                                 const float* __restrict__ z_j) {
    int row  = blockIdx.x * blockDim.y + threadIdx.y;
    int lane = threadIdx.x;
    const float* src = (row < BHALF) ? (z_i + (size_t)row * DDIM)
                                     : (z_j + (size_t)(row - BHALF) * DDIM);
    const float4* s4 = (const float4*)src;
    float4 v0 = s4[lane];
    float4 v1 = s4[lane + 32];
    float ss = v0.x*v0.x + v0.y*v0.y + v0.z*v0.z + v0.w*v0.w
             + v1.x*v1.x + v1.y*v1.y + v1.z*v1.z + v1.w*v1.w;
    #pragma unroll
    for (int o = 16; o > 0; o >>= 1) ss += __shfl_xor_sync(0xffffffffu, ss, o);
    float inv = 1.0f / fmaxf(sqrtf(ss), 1e-8f);
    float scf = 3.1622776601683795f * inv;   // 1/sqrt(0.1)
    float scb = 3.7982829f * inv;            // sqrt(10*log2(e))

    float4* d4 = (float4*)(g_zn + (size_t)row * DDIM);
    float4 w0 = { v0.x*scf, v0.y*scf, v0.z*scf, v0.w*scf };
    float4 w1 = { v1.x*scf, v1.y*scf, v1.z*scf, v1.w*scf };
    d4[lane]      = w0;
    d4[lane + 32] = w1;

    uint2 b0, b1;
    *(__nv_bfloat162*)&b0.x = __floats2bfloat162_rn(v0.x*scb, v0.y*scb);
    *(__nv_bfloat162*)&b0.y = __floats2bfloat162_rn(v0.z*scb, v0.w*scb);
    *(__nv_bfloat162*)&b1.x = __floats2bfloat162_rn(v1.x*scb, v1.y*scb);
    *(__nv_bfloat162*)&b1.y = __floats2bfloat162_rn(v1.z*scb, v1.w*scb);
    uint2* db = (uint2*)(g_znb + (size_t)row * DDIM);
    db[lane]      = b0;
    db[lane + 32] = b1;
}

// ---------------------------------------------------------------------------
// Kernel 2: symmetric bf16 mma.sync GEMM over the upper triangle of the
// 64x64 block grid, with fused sum-of-exp2 epilogue producing BOTH row sums
// (-> slot bj) and column sums (-> slot bi). 148 CTAs x 14-15 tiles.
// ---------------------------------------------------------------------------
__global__ __launch_bounds__(256, 1) void gemm_lse_sym() {
    extern __shared__ __align__(1024) char smem[];
    char* Asm  = smem;
    char* Bsm0 = smem + TILEB;
    char* Bsm1 = smem + 2 * TILEB;
    __shared__ float rs[2][128];   // row-sum partials per wy half
    __shared__ float cs[4][128];   // col-sum partials per wx band

    const int tid  = threadIdx.x;
    const int w    = tid >> 5;
    const int lane = tid & 31;
    const int wx   = w & 3;           // M band (32 rows)
    const int wy   = w >> 2;          // N band (64 cols)

    // ---- tile range for this CTA (8 CTAs x 15 tiles, 140 x 14) ----
    int t0, cnt;
    if (blockIdx.x < 8) { t0 = blockIdx.x * 15;              cnt = 15; }
    else                { t0 = 120 + (blockIdx.x - 8) * 14;  cnt = 14; }

    // locate (bi, bj) of tile t0 in row-major triangle order
    int bi = 0, accum = 0;
    while (accum + (NBLK - bi) <= t0) { accum += NBLK - bi; ++bi; }
    int bj = bi + (t0 - accum);

    const uint32_t Abase  = s2u(Asm);
    const uint32_t Bbase0 = s2u(Bsm0);
    const uint32_t Bbase1 = s2u(Bsm1);

    // ---- prologue loads ----
    load_blk(Abase, bi, tid);
    uint32_t curB;
    int pb;
    if (bj == bi) { curB = Abase;  pb = 0; }
    else          { load_blk(Bbase0, bj, tid); curB = Bbase0; pb = 1; }
    cp_commit();

    // ldmatrix lane geometry (as validated in round 4)
    const int tile  = lane >> 3;
    const int l7    = lane & 7;
    const int a_row = wx * 32 + (tile & 1) * 8 + l7;
    const int a_kh  = tile >> 1;
    const int b_row = wy * 64 + (tile >> 1) * 8 + l7;
    const int b_kh  = tile & 1;

    for (int it = 0; it < cnt; ++it) {
        const bool have_next = (it + 1 < cnt);
        int nbi = bi, nbj = bj + 1;
        if (nbj == NBLK) { nbi = bi + 1; nbj = nbi; }

        uint32_t nextB = 0;
        if (have_next && nbi == bi) {
            nextB = pb ? Bbase1 : Bbase0;
            load_blk(nextB, nbj, tid);
            cp_commit();
            pb ^= 1;
            cp_wait<1>();
        } else {
            cp_wait<0>();
        }
        __syncthreads();

        // ---- MMA: C = A_bi . B_bj^T (128x128, K=256) ----
        float acc[2][8][4];
        #pragma unroll
        for (int mt = 0; mt < 2; ++mt)
            #pragma unroll
            for (int nt = 0; nt < 8; ++nt)
                #pragma unroll
                for (int j = 0; j < 4; ++j) acc[mt][nt][j] = 0.f;

        #pragma unroll
        for (int ks = 0; ks < 16; ++ks) {
            uint32_t a[2][4];
            #pragma unroll
            for (int mt = 0; mt < 2; ++mt)
                LDSM4(a[mt][0], a[mt][1], a[mt][2], a[mt][3],
                      Abase + sw_off(a_row + mt * 16, ks * 2 + a_kh));
            uint32_t b[8][2];
            #pragma unroll
            for (int np = 0; np < 4; ++np) {
                uint32_t r0, r1, r2, r3;
                LDSM4(r0, r1, r2, r3,
                      curB + sw_off(b_row + np * 16, ks * 2 + b_kh));
                b[2*np][0] = r0;   b[2*np][1] = r1;
                b[2*np+1][0] = r2; b[2*np+1][1] = r3;
            }
            #pragma unroll
            for (int mt = 0; mt < 2; ++mt)
                #pragma unroll
                for (int nt = 0; nt < 8; ++nt)
                    MMA16816(acc[mt][nt], a[mt], b[nt]);
        }

        // ---- epilogue: exp2, row sums + col sums ----
        const bool isdiag = (bi == bj);
        float rsum[2][2] = {{0.f,0.f},{0.f,0.f}};   // [mt][j>>1]
        float csum[8][2] = {};                      // [nt][j&1]
        #pragma unroll
        for (int mt = 0; mt < 2; ++mt)
            #pragma unroll
            for (int nt = 0; nt < 8; ++nt)
                #pragma unroll
                for (int j = 0; j < 4; ++j) {
                    float e = ex2(acc[mt][nt][j]);
                    if (isdiag) {
                        int lr = wx*32 + (lane>>2) + mt*16 + (j>>1)*8;
                        int lc = wy*64 + nt*8 + (lane&3)*2 + (j&1);
                        if (lr == lc) e = 0.f;
                    }
                    rsum[mt][j>>1] += e;
                    csum[nt][j&1]  += e;
                }

        // row sums: reduce over the 4 lanes of a quad (xor 1,2)
        #pragma unroll
        for (int mt = 0; mt < 2; ++mt)
            #pragma unroll
            for (int rh = 0; rh < 2; ++rh) {
                float v = rsum[mt][rh];
                v += __shfl_xor_sync(0xffffffffu, v, 1);
                v += __shfl_xor_sync(0xffffffffu, v, 2);
                rsum[mt][rh] = v;
            }
        // col sums: reduce over the 8 row-lanes (xor 4,8,16)
        #pragma unroll
        for (int nt = 0; nt < 8; ++nt)
            #pragma unroll
            for (int jp = 0; jp < 2; ++jp) {
                float v = csum[nt][jp];
                v += __shfl_xor_sync(0xffffffffu, v, 4);
                v += __shfl_xor_sync(0xffffffffu, v, 8);
                v += __shfl_xor_sync(0xffffffffu, v, 16);
                csum[nt][jp] = v;
            }

        if ((lane & 3) == 0) {
            #pragma unroll
            for (int mt = 0; mt < 2; ++mt)
                #pragma unroll
                for (int rh = 0; rh < 2; ++rh)
                    rs[wy][wx*32 + mt*16 + rh*8 + (lane>>2)] = rsum[mt][rh];
        }
        if (lane < 4) {
            #pragma unroll
            for (int nt = 0; nt < 8; ++nt)
                #pragma unroll
                for (int jp = 0; jp < 2; ++jp)
                    cs[wx][wy*64 + nt*8 + lane*2 + jp] = csum[nt][jp];
        }
        __syncthreads();

        if (tid < 128) {
            g_part[bj * NTOT + bi * 128 + tid] = rs[0][tid] + rs[1][tid];
        } else if (!isdiag) {
            int c = tid - 128;
            g_part[bi * NTOT + bj * 128 + c]
                = (cs[0][c] + cs[1][c]) + (cs[2][c] + cs[3][c]);
        }
        __syncthreads();   // rs/cs + B buffer free for next iteration

        if (have_next) {
            if (nbi == bi) {
                curB = nextB;
            } else {
                load_blk(Abase, nbi, tid);   // row cross: reload A (exposed)
                cp_commit();
                curB = Abase;                // next tile is diagonal: B = A
            }
            bi = nbi; bj = nbj;
        }
    }
}

// ---------------------------------------------------------------------------
// Kernel 3: loss_k = ln2*log2(sum_t g_part[t][k]) - dot_fp32(zn_k, zn_pos)
// plus per-block masked partials for the final mean. 1024 blocks x (32,8).
// ---------------------------------------------------------------------------
__global__ void finalize_kernel(const int* __restrict__ mask) {
    __shared__ float2 wres[8];
    int row  = blockIdx.x * 8 + threadIdx.y;
    int lane = threadIdx.x;
    int pos  = (row < BHALF) ? row + BHALF : row - BHALF;

    const float4* a4 = (const float4*)(g_zn + (size_t)row * DDIM);
    const float4* b4 = (const float4*)(g_zn + (size_t)pos * DDIM);
    float dot = 0.0f;
    #pragma unroll
    for (int t = 0; t < 2; ++t) {
        float4 a = a4[lane + 32 * t];
        float4 b = b4[lane + 32 * t];
        dot += a.x*b.x + a.y*b.y + a.z*b.z + a.w*b.w;
    }
    float p = g_part[lane * NTOT + row] + g_part[(lane + 32) * NTOT + row];
    #pragma unroll
    for (int o = 16; o > 0; o >>= 1) {
        dot += __shfl_xor_sync(0xffffffffu, dot, o);
        p   += __shfl_xor_sync(0xffffffffu, p, o);
    }
    if (lane == 0) {
        float loss = 0.6931471805599453f * log2f(p) - dot;
        float m = (mask[row & (BHALF - 1)] != 0) ? 1.0f : 0.0f;
        wres[threadIdx.y] = make_float2(loss * m, m);
    }
    __syncthreads();
    if (threadIdx.y == 0 && lane == 0) {
        float s = 0.f, c = 0.f;
        #pragma unroll
        for (int i = 0; i < 8; ++i) { s += wres[i].x; c += wres[i].y; }
        g_red[blockIdx.x] = make_float2(s, c);
    }
}

// ---------------------------------------------------------------------------
// Kernel 4: deterministic final mean over 1024 block partials.
// ---------------------------------------------------------------------------
__global__ void reduce_kernel(float* __restrict__ out) {
    __shared__ float ssum[1024];
    __shared__ float scnt[1024];
    int tid = threadIdx.x;
    float2 v = g_red[tid];
    ssum[tid] = v.x; scnt[tid] = v.y;
    __syncthreads();
    for (int s = 512; s > 0; s >>= 1) {
        if (tid < s) { ssum[tid] += ssum[tid + s]; scnt[tid] += scnt[tid + s]; }
        __syncthreads();
    }
    if (tid == 0)
        out[0] = (scnt[0] > 0.0f) ? ssum[0] / fmaxf(scnt[0], 1.0f) : 0.0f;
}

// ---------------------------------------------------------------------------
extern "C" void kernel_launch(void* const* d_in, const int* in_sizes, int n_in,
                              void* d_out, int out_size) {
    const float* z_i  = (const float*)d_in[0];
    const float* z_j  = (const float*)d_in[1];
    const int*   mask = (const int*)d_in[2];
    float* out = (float*)d_out;
    (void)in_sizes; (void)n_in; (void)out_size;

    cudaFuncSetAttribute(gemm_lse_sym,
                         cudaFuncAttributeMaxDynamicSharedMemorySize,
                         SMEM_TOTAL);

    dim3 warpBlock(32, 8);
    normalize_kernel<<<NTOT / 8, warpBlock>>>(z_i, z_j);
    gemm_lse_sym<<<148, 256, SMEM_TOTAL>>>();
    finalize_kernel<<<1024, warpBlock>>>(mask);
    reduce_kernel<<<1, 1024>>>(out);
}